// round 17
// baseline (speedup 1.0000x reference)
#include <cuda_runtime.h>
#include <cuda_fp16.h>
#include <cstdint>

#define NN      4096
#define FIN     256
#define FOUT    64
#define HEADS   4
#define NF      (NN * FOUT)
#define ITILE   128
#define JCHUNK  64
#define NSPLIT  2
#define NCHUNK  (NN / NSPLIT / JCHUNK)   // 32 chunks per block
#define NGRP    (NN / 128)               // 32 mask groups (uint4) per adj row
#define HT_B    (FOUT * JCHUNK * 2)      // 8192 bytes per Ht buffer
#define GR      16                       // rows per gemm_h block

// ---------------- device scratch ----------------
__device__ float4 g_i4[NN * HEADS];            // {ei, exp(ei), exp(.2ei), 0}
__device__ uint2  g_jh2[HEADS * (NN / 2)];     // per (head, node-pair): {E2, N2} half2s
__device__ __half g_hT[HEADS * FOUT * NN];     // transposed h, fp16
__device__ __half g_WThl[2 * 256 * 256];       // W^T fp16: hi at 0, lo at 65536; [n][k]
__device__ uint4  g_adjb4[NN * NGRP];          // 4 ballot words: word k bit l <-> col 128g+4l+k
__device__ float  g_partC[NSPLIT * HEADS * NN * FOUT];
__device__ float  g_partZ[NSPLIT * HEADS * NN];

// ---------------- PTX helpers ----------------
__device__ __forceinline__ uint32_t smem_u32(const void* p) {
    uint32_t a;
    asm("{ .reg .u64 t; cvta.to.shared.u64 t, %1; cvt.u32.u64 %0, t; }" : "=r"(a) : "l"(p));
    return a;
}
__device__ __forceinline__ void ldsm4(uint32_t* r, uint32_t addr) {
    asm volatile("ldmatrix.sync.aligned.m8n8.x4.shared.b16 {%0,%1,%2,%3}, [%4];"
                 : "=r"(r[0]), "=r"(r[1]), "=r"(r[2]), "=r"(r[3]) : "r"(addr));
}
__device__ __forceinline__ void ldsm2(uint32_t& r0, uint32_t& r1, uint32_t addr) {
    asm volatile("ldmatrix.sync.aligned.m8n8.x2.shared.b16 {%0,%1}, [%2];"
                 : "=r"(r0), "=r"(r1) : "r"(addr));
}
__device__ __forceinline__ void mma16816(float* c, const uint32_t* a,
                                         uint32_t b0, uint32_t b1) {
    asm volatile("mma.sync.aligned.m16n8k16.row.col.f32.f16.f16.f32 "
                 "{%0,%1,%2,%3}, {%4,%5,%6,%7}, {%8,%9}, {%0,%1,%2,%3};"
                 : "+f"(c[0]), "+f"(c[1]), "+f"(c[2]), "+f"(c[3])
                 : "r"(a[0]), "r"(a[1]), "r"(a[2]), "r"(a[3]), "r"(b0), "r"(b1));
}
#define CP_ASYNC16(dst, src) \
    asm volatile("cp.async.cg.shared.global [%0], [%1], 16;" :: "r"(dst), "l"(src) : "memory")
#define CP_ASYNC8(dst, src) \
    asm volatile("cp.async.ca.shared.global [%0], [%1], 8;"  :: "r"(dst), "l"(src) : "memory")
#define CP_COMMIT() asm volatile("cp.async.commit_group;" ::: "memory")
#define CP_WAIT1()  asm volatile("cp.async.wait_group 1;"  ::: "memory")
// XOR swizzle for 128B rows (gat Ht)
__device__ __forceinline__ uint32_t swz(int row, int byteInRow) {
    return (uint32_t)(row * 128 + ((((byteInRow >> 4) ^ (row & 7)) << 4) | (byteInRow & 15)));
}
__device__ __forceinline__ unsigned pack2h(float a, float b) {
    return ((unsigned)__half_as_ushort(__float2half_rn(b)) << 16) |
           __half_as_ushort(__float2half_rn(a));
}
// w2 = max(Ei*Ej, Ni*Nj) in half2, then AND with 2-bit-derived lane mask
__device__ __forceinline__ uint32_t wgen(__half2 hE, __half2 hN,
                                         uint32_t Ep, uint32_t Np, unsigned b2) {
    const __half2 Eh = *reinterpret_cast<const __half2*>(&Ep);
    const __half2 Nh = *reinterpret_cast<const __half2*>(&Np);
    const __half2 w2 = __hmax2(__hmul2(hE, Eh), __hmul2(hN, Nh));
    const uint32_t m = ((b2 & 1u) * 0xFFFFu) | (((b2 >> 1) & 1u) * 0xFFFF0000u);
    return (*reinterpret_cast<const uint32_t*>(&w2)) & m;
}

// ---------------- kernel 0: W -> W^T fp16 hi/lo ----------------
__global__ void __launch_bounds__(256) w_prep_kernel(const float* __restrict__ W) {
    __shared__ float ws[8][257];
    const int kb = blockIdx.x;         // k rows kb*8 .. +8
    const int t  = threadIdx.x;        // = n
    #pragma unroll
    for (int kk = 0; kk < 8; ++kk)
        ws[kk][t] = W[(kb * 8 + kk) * 256 + t];
    __syncthreads();
    unsigned hp[4], lp[4];
    #pragma unroll
    for (int kk = 0; kk < 8; kk += 2) {
        const float v0 = ws[kk][t], v1 = ws[kk + 1][t];
        const __half h0 = __float2half_rn(v0), h1 = __float2half_rn(v1);
        hp[kk >> 1] = ((unsigned)__half_as_ushort(h1) << 16) | __half_as_ushort(h0);
        lp[kk >> 1] = pack2h(v0 - __half2float(h0), v1 - __half2float(h1));
    }
    *(uint4*)&g_WThl[(size_t)t * 256 + kb * 8]         = make_uint4(hp[0], hp[1], hp[2], hp[3]);
    *(uint4*)&g_WThl[65536 + (size_t)t * 256 + kb * 8] = make_uint4(lp[0], lp[1], lp[2], lp[3]);
}

// ---------------- kernel 1: HMMA x@W + hT + e-scores + coalesced pack ----------
// smem map (GS): A_hi [0,8192), A_lo [8192,16384), B stages 3x8192 [16384,40960);
// post-GEMM the B region is reused as hs_f[256][17] fp32.
__global__ void __launch_bounds__(256) gemm_h_kernel(const float* __restrict__ x,
                                                     const float* __restrict__ a,
                                                     const int* __restrict__ adj) {
    __shared__ __align__(128) char GS[40960];
    __shared__ float as[128];
    const int t    = threadIdx.x;
    const int lane = t & 31;
    const int ww   = t >> 5;
    const int n0   = blockIdx.x * GR;
    const uint32_t gsb = smem_u32(GS);

    if (t < 128) as[t] = a[t];

    // prologue: B stages 0,1 (virtual stage s: hl=s&1, kc=s>>1; 8KB each)
    #pragma unroll
    for (int s = 0; s < 2; ++s) {
        const int hl = s & 1, kc = s >> 1;
        const __half* src = g_WThl + hl * 65536 + (size_t)t * 256 + kc * 16;
        const uint32_t dst = gsb + 16384 + (s % 3) * 8192 + t * 32;
        CP_ASYNC16(dst, src);
        CP_ASYNC16(dst + 16, src + 8);
        CP_COMMIT();
    }

    // A: x rows n0..n0+15 -> fp16 hi/lo, swizzled 512B rows (chunk ^= row&7)
    #pragma unroll
    for (int u = 0; u < 2; ++u) {
        const int ch = 2 * t + u;          // 0..511
        const int r  = ch >> 5;
        const int c  = ch & 31;
        const float4 v0 = *(const float4*)&x[(size_t)(n0 + r) * 256 + c * 8];
        const float4 v1 = *(const float4*)&x[(size_t)(n0 + r) * 256 + c * 8 + 4];
        const __half h0 = __float2half_rn(v0.x), h1 = __float2half_rn(v0.y);
        const __half h2 = __float2half_rn(v0.z), h3 = __float2half_rn(v0.w);
        const __half h4 = __float2half_rn(v1.x), h5 = __float2half_rn(v1.y);
        const __half h6 = __float2half_rn(v1.z), h7 = __float2half_rn(v1.w);
        const uint4 hq = make_uint4(
            ((unsigned)__half_as_ushort(h1) << 16) | __half_as_ushort(h0),
            ((unsigned)__half_as_ushort(h3) << 16) | __half_as_ushort(h2),
            ((unsigned)__half_as_ushort(h5) << 16) | __half_as_ushort(h4),
            ((unsigned)__half_as_ushort(h7) << 16) | __half_as_ushort(h6));
        const uint4 lq = make_uint4(
            pack2h(v0.x - __half2float(h0), v0.y - __half2float(h1)),
            pack2h(v0.z - __half2float(h2), v0.w - __half2float(h3)),
            pack2h(v1.x - __half2float(h4), v1.y - __half2float(h5)),
            pack2h(v1.z - __half2float(h6), v1.w - __half2float(h7)));
        const uint32_t off = (uint32_t)(r * 512 + ((c ^ (r & 7)) << 4));
        *(uint4*)(GS + off)        = hq;
        *(uint4*)(GS + 8192 + off) = lq;
    }

    // warp GEMM coords: warp owns cols ncol0..+32 (4 n-tiles), all 16 rows
    const int grp   = lane >> 3;
    const int tid   = lane & 3;
    const int gr    = lane >> 2;
    const int ncol0 = ww * 32;
    const int rofs  = (grp >> 1) * 8 + (lane & 7);
    const int cofs  = (grp & 1) * 16;
    const int arow  = lane & 15;

    float acc[4][4];
    #pragma unroll
    for (int n = 0; n < 4; ++n)
        #pragma unroll
        for (int k = 0; k < 4; ++k) acc[n][k] = 0.0f;

    for (int s = 0; s < 32; ++s) {
        CP_WAIT1();
        __syncthreads();
        if (s + 2 < 32) {
            const int s2 = s + 2, hl2 = s2 & 1, kc2 = s2 >> 1;
            const __half* src = g_WThl + hl2 * 65536 + (size_t)t * 256 + kc2 * 16;
            const uint32_t dst = gsb + 16384 + (s2 % 3) * 8192 + t * 32;
            CP_ASYNC16(dst, src);
            CP_ASYNC16(dst + 16, src + 8);
        }
        CP_COMMIT();

        const int hl = s & 1, kc = s >> 1;
        const uint32_t bb = gsb + 16384 + (s % 3) * 8192;
        uint32_t bf0[4], bf1[4];
        ldsm4(bf0, bb + (ncol0 + rofs) * 32 + cofs);        // n-tiles 0,1
        ldsm4(bf1, bb + (ncol0 + 16 + rofs) * 32 + cofs);   // n-tiles 2,3
        const uint32_t aoff =
            (uint32_t)(arow * 512 + (((2 * kc + (lane >> 4)) ^ (arow & 7)) << 4));
        uint32_t ah[4];
        ldsm4(ah, gsb + aoff);
        mma16816(acc[0], ah, bf0[0], bf0[1]);
        mma16816(acc[1], ah, bf0[2], bf0[3]);
        mma16816(acc[2], ah, bf1[0], bf1[1]);
        mma16816(acc[3], ah, bf1[2], bf1[3]);
        if (hl == 0) {      // B = W_hi: also accumulate x_lo @ W_hi
            uint32_t al[4];
            ldsm4(al, gsb + 8192 + aoff);
            mma16816(acc[0], al, bf0[0], bf0[1]);
            mma16816(acc[1], al, bf0[2], bf0[3]);
            mma16816(acc[2], al, bf1[0], bf1[1]);
            mma16816(acc[3], al, bf1[2], bf1[3]);
        }
    }

    // ---- epilogue: acc -> hs_f[col][17] (reuse B region) ----
    __syncthreads();
    float* hs = (float*)(GS + 16384);
    #pragma unroll
    for (int nt = 0; nt < 4; ++nt) {
        const int col = ncol0 + nt * 8 + 2 * tid;
        hs[col * 17 + gr]           = acc[nt][0];
        hs[(col + 1) * 17 + gr]     = acc[nt][1];
        hs[col * 17 + gr + 8]       = acc[nt][2];
        hs[(col + 1) * 17 + gr + 8] = acc[nt][3];
    }
    __syncthreads();

    // hT: thread t = col, 16 rows -> 32B store
    {
        unsigned hp[8];
        #pragma unroll
        for (int r = 0; r < 16; r += 2)
            hp[r >> 1] = pack2h(hs[t * 17 + r], hs[t * 17 + r + 1]);
        uint4* dh = (uint4*)&g_hT[(size_t)t * NN + n0];
        dh[0] = make_uint4(hp[0], hp[1], hp[2], hp[3]);
        dh[1] = make_uint4(hp[4], hp[5], hp[6], hp[7]);
    }

    // e-scores
    if (t < 128) {
        const int r     = t >> 3;        // 0..15
        const int g     = t & 7;
        const int hd    = g >> 1;
        const int which = g & 1;
        const float* av = as + which * 64;
        const float* hr = hs + hd * 64 * 17 + r;
        float s = 0.0f;
        #pragma unroll
        for (int f = 0; f < 64; ++f) s = fmaf(hr[f * 17], av[f], s);
        const int n = n0 + r;
        const float E = __expf(s);
        const float N = __expf(0.2f * s);
        if (which == 0) {
            g_i4[n * HEADS + hd] = make_float4(s, E, N, 0.0f);
        } else {
            __half* jb = (__half*)&g_jh2[(size_t)hd * (NN / 2) + (n >> 1)];
            jb[n & 1]       = __float2half_rn(E);
            jb[2 + (n & 1)] = __float2half_rn(N);
        }
    }

    // ---- coalesced ballot pack: warp ww packs rows n0+2ww, n0+2ww+1 ----
    #pragma unroll
    for (int rr = 0; rr < 2; ++rr) {
        const int row = n0 + 2 * ww + rr;
        const int4* src = (const int4*)(adj + (size_t)row * NN);
        uint4* dst = &g_adjb4[(size_t)row * NGRP];
        for (int m = 0; m < NGRP; m += 8) {
            int4 v[8];
            #pragma unroll
            for (int q = 0; q < 8; ++q)
                v[q] = src[(m + q) * 32 + lane];     // 8 coalesced LDG.128 in flight
            uint4 bw[8];
            #pragma unroll
            for (int q = 0; q < 8; ++q) {
                bw[q].x = __ballot_sync(0xffffffffu, v[q].x != 0);
                bw[q].y = __ballot_sync(0xffffffffu, v[q].y != 0);
                bw[q].z = __ballot_sync(0xffffffffu, v[q].z != 0);
                bw[q].w = __ballot_sync(0xffffffffu, v[q].w != 0);
            }
            if (lane == 0) {
                #pragma unroll
                for (int q = 0; q < 8; ++q) dst[m + q] = bw[q];
            }
        }
    }
}

// ---------------- kernel 2: register-gen mma attention (unchanged from r16) --------
__global__ void __launch_bounds__(256, 2) gat_mma_kernel() {
    __shared__ __align__(128) __half  Ht[3][FOUT * JCHUNK];
    __shared__ __align__(16)  uint2   jsm[3][JCHUNK / 2];
    __shared__ __align__(32)  __half  OnesT[8][16];

    const int t     = threadIdx.x;
    const int lane  = t & 31;
    const int w     = t >> 5;
    const int tid   = lane & 3;
    const int gr    = lane >> 2;
    const int head  = blockIdx.y;
    const int i0    = blockIdx.x * ITILE;
    const int split = blockIdx.z;
    const int jbase = split * (NN / NSPLIT);

    const uint32_t htb = smem_u32(Ht);
    const uint32_t onb = smem_u32(OnesT);

    if (t < 128) ((__half*)OnesT)[t] = (t < 16) ? __float2half(1.0f) : __float2half(0.0f);

    const int rA = w * 16 + gr;
    const float4 e0 = g_i4[(i0 + rA) * HEADS + head];
    const float4 e1 = g_i4[(i0 + rA + 8) * HEADS + head];
    const __half2 hE0 = __float2half2_rn(e0.y), hN0 = __float2half2_rn(e0.z);
    const __half2 hE1 = __float2half2_rn(e1.y), hN1 = __float2half2_rn(e1.z);

    const int hrow = t >> 2;
    const int s0   = (t & 3) * 2;
    const __half* hsrc = &g_hT[(size_t)(head * FOUT + hrow) * NN + jbase];
    const uint2* jsrc = &g_jh2[(size_t)head * (NN / 2) + jbase / 2];

    const uint4* adjp0 = &g_adjb4[(size_t)(i0 + rA) * NGRP + split * (NCHUNK / 2)];
    const uint4* adjp1 = &g_adjb4[(size_t)(i0 + rA + 8) * NGRP + split * (NCHUNK / 2)];
    uint4 awc0 = adjp0[0], awc1 = adjp1[0];
    uint4 awn0, awn1;

    float acc[8][4];
    #pragma unroll
    for (int n = 0; n < 8; ++n)
        #pragma unroll
        for (int k = 0; k < 4; ++k) acc[n][k] = 0.0f;
    float accZ[4] = {0.0f, 0.0f, 0.0f, 0.0f};

    #pragma unroll
    for (int pc = 0; pc < 2; ++pc) {
        const uint32_t hb = htb + pc * HT_B;
        CP_ASYNC16(hb + swz(hrow, s0 * 16),       hsrc + pc * JCHUNK + s0 * 8);
        CP_ASYNC16(hb + swz(hrow, (s0 + 1) * 16), hsrc + pc * JCHUNK + (s0 + 1) * 8);
        if (t < JCHUNK / 2)
            CP_ASYNC8(smem_u32(&jsm[pc][t]), jsrc + pc * (JCHUNK / 2) + t);
        CP_COMMIT();
    }

    __syncthreads();
    uint32_t oz0, oz1;
    ldsm2(oz0, oz1, onb + (lane & 7) * 32 + ((lane >> 3) & 1) * 16);

    for (int c = 0; c < NCHUNK; ++c) {
        const int b = c % 3;
        CP_WAIT1();
        __syncthreads();

        if (c + 2 < NCHUNK) {
            const int b2 = (c + 2) % 3;
            const uint32_t hb = htb + b2 * HT_B;
            CP_ASYNC16(hb + swz(hrow, s0 * 16),       hsrc + (c + 2) * JCHUNK + s0 * 8);
            CP_ASYNC16(hb + swz(hrow, (s0 + 1) * 16), hsrc + (c + 2) * JCHUNK + (s0 + 1) * 8);
            if (t < JCHUNK / 2)
                CP_ASYNC8(smem_u32(&jsm[b2][t]), jsrc + (c + 2) * (JCHUNK / 2) + t);
        }
        CP_COMMIT();

        if ((c & 1) && (c + 1 < NCHUNK)) {
            awn0 = adjp0[(c + 1) >> 1];
            awn1 = adjp1[(c + 1) >> 1];
        }

        const uint32_t hb = htb + b * HT_B;
        const uint2* jrow = jsm[b];

        const unsigned wlo0 = (tid & 1) ? awc0.z : awc0.x;
        const unsigned whi0 = (tid & 1) ? awc0.w : awc0.y;
        const unsigned wlo1 = (tid & 1) ? awc1.z : awc1.x;
        const unsigned whi1 = (tid & 1) ? awc1.w : awc1.y;
        const int pbase = (c & 1) * 16 + (tid >> 1);

        #pragma unroll
        for (int ks = 0; ks < 4; ++ks) {
            uint32_t bf[4][4];
            {
                const int grp  = lane >> 3;
                const int bkcB = (ks * 2 + (grp & 1)) * 16;
                const int rofs = (grp >> 1) * 8 + (lane & 7);
                #pragma unroll
                for (int np = 0; np < 4; ++np)
                    ldsm4(bf[np], hb + swz(np * 16 + rofs, bkcB));
            }
            const uint2 jA = jrow[ks * 8 + tid];
            const uint2 jB = jrow[ks * 8 + tid + 4];
            const int p = pbase + ks * 4;
            const unsigned sl0 = wlo0 >> p, sh0 = whi0 >> p;
            const unsigned sl1 = wlo1 >> p, sh1 = whi1 >> p;
            const unsigned b2A0 = (sl0 & 1u) | ((sh0 & 1u) << 1);
            const unsigned b2A1 = (sl1 & 1u) | ((sh1 & 1u) << 1);
            const unsigned b2B0 = ((sl0 >> 2) & 1u) | (((sh0 >> 2) & 1u) << 1);
            const unsigned b2B1 = ((sl1 >> 2) & 1u) | (((sh1 >> 2) & 1u) << 1);
            uint32_t af[4];
            af[0] = wgen(hE0, hN0, jA.x, jA.y, b2A0);
            af[1] = wgen(hE1, hN1, jA.x, jA.y, b2A1);
            af[2] = wgen(hE0, hN0, jB.x, jB.y, b2B0);
            af[3] = wgen(hE1, hN1, jB.x, jB.y, b2B1);
            #pragma unroll
            for (int np = 0; np < 4; ++np) {
                mma16816(acc[np * 2],     af, bf[np][0], bf[np][1]);
                mma16816(acc[np * 2 + 1], af, bf[np][2], bf[np][3]);
            }
            mma16816(accZ, af, oz0, oz1);
        }
        if (c & 1) { awc0 = awn0; awc1 = awn1; }
    }

    if (tid == 0) {
        float* zb = g_partZ + (size_t)(split * HEADS + head) * NN + i0;
        zb[rA]     = accZ[0];
        zb[rA + 8] = accZ[2];
    }

    {
        float* cbase = g_partC + (size_t)(split * HEADS + head) * NN * FOUT;
        float* p0 = cbase + (size_t)(i0 + rA) * FOUT + 2 * tid;
        float* p1 = cbase + (size_t)(i0 + rA + 8) * FOUT + 2 * tid;
        #pragma unroll
        for (int np = 0; np < 4; ++np) {
            #pragma unroll
            for (int p = 0; p < 2; ++p) {
                const int nt = np * 2 + p;
                const int cb = np * 16 + p * 8;
                *(float2*)(p0 + cb) = make_float2(acc[nt][0], acc[nt][1]);
                *(float2*)(p1 + cb) = make_float2(acc[nt][2], acc[nt][3]);
            }
        }
    }
}

// ---------------- kernel 3: combine splits, normalize, mean heads ----------
__global__ void __launch_bounds__(256) combine_kernel(float* __restrict__ out) {
    const int idx = blockIdx.x * 256 + threadIdx.x;
    const int i = idx >> 6;
    float r = 0.0f;
    #pragma unroll
    for (int h = 0; h < HEADS; ++h) {
        float cs = 0.0f, zs = 0.0f;
        #pragma unroll
        for (int s = 0; s < NSPLIT; ++s) {
            cs += g_partC[(size_t)(s * HEADS + h) * NN * FOUT + idx];
            zs += g_partZ[(size_t)(s * HEADS + h) * NN + i];
        }
        r += cs / zs;
    }
    out[idx] = 0.25f * r;
}

// ---------------- launcher ----------------
extern "C" void kernel_launch(void* const* d_in, const int* in_sizes, int n_in,
                              void* d_out, int out_size) {
    const float* x = nullptr;
    const int*   adj = nullptr;
    const float* W = nullptr;
    const float* a = nullptr;
    for (int i = 0; i < n_in; ++i) {
        switch (in_sizes[i]) {
            case 1048576:  x   = (const float*)d_in[i]; break;
            case 16777216: adj = (const int*)  d_in[i]; break;
            case 65536:    W   = (const float*)d_in[i]; break;
            case 128:      a   = (const float*)d_in[i]; break;
        }
    }
    float* out = (float*)d_out;

    w_prep_kernel<<<32, 256>>>(W);
    gemm_h_kernel<<<NN / GR, 256>>>(x, a, adj);
    gat_mma_kernel<<<dim3(NN / ITILE, HEADS, NSPLIT), 256>>>();
    combine_kernel<<<NF / 256, 256>>>(out);
}